// round 10
// baseline (speedup 1.0000x reference)
#include <cuda_runtime.h>
#include <cuda_bf16.h>
#include <cstdint>

// ============================================================================
// SimplifiedTopologyExtractor — algebraic reduction:
//   out = ReLU(LayerNorm(emb[:, :, :256] @ W_enc + b_enc))
// (pooled == embeddings exactly; proj/cdist/topk is dead code.)
//
// fp32 GEMM via bf16 hi/lo split on mma.sync m16n8k16:
//   a*b ≈ ah*bh + ah*bl + al*bh   (err ~2^-18 rel).
// Round 10: R8 sync'd skeleton + (a) A converted to smem once up front,
// (b) warp grid 2x8 (tile m32n64) cutting per-SM LDSM traffic 147->96KB
// (B read 2x instead of 4x), (c) 4-stage bulk-copy B ring, 3 ahead.
// ============================================================================

#define THREADS 512
#define MTILE 64
#define KD 256
#define KCH 16
#define NCHUNK (KD / KCH)
#define STAGES 4
#define B_CHUNK 32768

// smem layout (bytes)
#define OFF_A     0                      // 16 chunks x 4096 (hi 2KB | lo 2KB)
#define OFF_B     65536                  // 4 stages x 32768
#define OFF_MBAR  (OFF_B + STAGES * B_CHUNK)    // 196608
#define OFF_PS    (OFF_MBAR + 64)
#define OFF_PQ    (OFF_PS + 2048)
#define OFF_MZ    (OFF_PQ + 2048)
#define SMEM_TOTAL (OFF_MZ + 512)        // 201280

// prepped B (bf16 hi/lo), chunk-shaped + XOR-unit swizzle:
//   [chunk 16][part 2][kr 16][unit 64], stored at unit ^ (kr&7)
__device__ __align__(128) unsigned char g_Bpre[16 * B_CHUNK];   // 512 KB

__device__ __forceinline__ uint32_t smem_u32(const void* p) {
    uint32_t a;
    asm("{ .reg .u64 t; cvta.to.shared.u64 t, %1; cvt.u32.u64 %0, t; }"
        : "=r"(a) : "l"(p));
    return a;
}

__device__ __forceinline__ void ldsm4(uint32_t* r, uint32_t addr) {
    asm volatile("ldmatrix.sync.aligned.m8n8.x4.shared.b16 {%0,%1,%2,%3}, [%4];"
                 : "=r"(r[0]), "=r"(r[1]), "=r"(r[2]), "=r"(r[3]) : "r"(addr));
}
__device__ __forceinline__ void ldsm4t(uint32_t* r, uint32_t addr) {
    asm volatile("ldmatrix.sync.aligned.m8n8.x4.trans.shared.b16 {%0,%1,%2,%3}, [%4];"
                 : "=r"(r[0]), "=r"(r[1]), "=r"(r[2]), "=r"(r[3]) : "r"(addr));
}

__device__ __forceinline__ void mma16816(float* d, const uint32_t* a,
                                         uint32_t b0, uint32_t b1) {
    asm volatile(
        "mma.sync.aligned.m16n8k16.row.col.f32.bf16.bf16.f32 "
        "{%0,%1,%2,%3}, {%4,%5,%6,%7}, {%8,%9}, {%0,%1,%2,%3};"
        : "+f"(d[0]), "+f"(d[1]), "+f"(d[2]), "+f"(d[3])
        : "r"(a[0]), "r"(a[1]), "r"(a[2]), "r"(a[3]), "r"(b0), "r"(b1));
}

#define MBAR_INIT(addr, cnt) \
    asm volatile("mbarrier.init.shared.b64 [%0], %1;" :: "r"(addr), "r"(cnt) : "memory")

#define MBAR_EXPECT_TX(addr, bytes) \
    asm volatile("mbarrier.arrive.expect_tx.shared.b64 _, [%0], %1;" \
                 :: "r"(addr), "r"((uint32_t)(bytes)) : "memory")

#define MBAR_WAIT(addr, par) do {                                              \
    uint32_t _m = (addr), _p = (uint32_t)(par), _done;                         \
    asm volatile("{\n\t.reg .pred p;\n\t"                                      \
        "mbarrier.try_wait.parity.acquire.cta.shared::cta.b64 p, [%1], %2;\n\t"\
        "selp.b32 %0, 1, 0, p;\n\t}" : "=r"(_done) : "r"(_m), "r"(_p) : "memory"); \
    if (!_done) {                                                              \
        asm volatile("{\n\t.reg .pred P1;\n\t"                                 \
            "W%=:\n\t"                                                         \
            "mbarrier.try_wait.parity.acquire.cta.shared::cta.b64 P1, [%0], %1, 0x989680;\n\t" \
            "@P1 bra.uni D%=;\n\t"                                             \
            "bra.uni W%=;\n\t"                                                 \
            "D%=:\n\t}" :: "r"(_m), "r"(_p) : "memory");                       \
    }                                                                          \
} while (0)

__device__ __forceinline__ void bulk_copy(uint32_t dst, const void* src,
                                          uint32_t bytes, uint32_t mbar) {
    asm volatile(
        "cp.async.bulk.shared::cluster.global.mbarrier::complete_tx::bytes "
        "[%0], [%1], %2, [%3];"
        :: "r"(dst), "l"(src), "r"(bytes), "r"(mbar) : "memory");
}

__device__ __forceinline__ void split_f4(float4 v, uint32_t& h01, uint32_t& h23,
                                         uint32_t& l01, uint32_t& l23) {
    float f[4] = {v.x, v.y, v.z, v.w};
    unsigned short hs[4], ls[4];
#pragma unroll
    for (int i = 0; i < 4; i++) {
        __nv_bfloat16 h = __float2bfloat16(f[i]);
        float rem = f[i] - __bfloat162float(h);
        __nv_bfloat16 l = __float2bfloat16(rem);
        hs[i] = __bfloat16_as_ushort(h);
        ls[i] = __bfloat16_as_ushort(l);
    }
    h01 = (uint32_t)hs[0] | ((uint32_t)hs[1] << 16);
    h23 = (uint32_t)hs[2] | ((uint32_t)hs[3] << 16);
    l01 = (uint32_t)ls[0] | ((uint32_t)ls[1] << 16);
    l23 = (uint32_t)ls[2] | ((uint32_t)ls[3] << 16);
}

// ---- prep B: W_enc[256,512] -> hi/lo bf16, chunk-tiled + XOR swizzle ----
__global__ void prep_b_kernel(const float* __restrict__ W) {
    int t = blockIdx.x * 256 + threadIdx.x;   // 256 k x 128 nq
    int k  = t >> 7;
    int nq = t & 127;
    float4 v = *(const float4*)(W + (size_t)k * 512 + nq * 4);
    uint32_t h01, h23, l01, l23;
    split_f4(v, h01, h23, l01, l23);
    int c = k >> 4, kr = k & 15;
    int unit = nq >> 1;
    int sw   = unit ^ (kr & 7);
    size_t base = (size_t)c * B_CHUNK + (size_t)kr * 1024
                + (size_t)sw * 16 + (nq & 1) * 8;
    *(uint2*)(g_Bpre + base)         = make_uint2(h01, h23);
    *(uint2*)(g_Bpre + base + 16384) = make_uint2(l01, l23);
}

// ---- GEMM + fused bias/LayerNorm/ReLU ----
__global__ void __launch_bounds__(THREADS, 1)
gemm_ln_kernel(const float* __restrict__ emb,
               const float* __restrict__ bias,
               const float* __restrict__ gamma,
               const float* __restrict__ beta,
               float* __restrict__ out)
{
    extern __shared__ __align__(1024) unsigned char smem[];
    const uint32_t sb = smem_u32(smem);
    const int tid = threadIdx.x;
    const int wid = tid >> 5;
    const int lane = tid & 31;
    const int mw = wid >> 3;       // 2 m-warps: rows mw*32..+32
    const int nw = wid & 7;        // 8 n-warps: cols nw*64..+64
    const int m0 = blockIdx.x * MTILE;

    float acc[2][8][4];            // [mt][ng][frag]
#pragma unroll
    for (int mt = 0; mt < 2; mt++)
#pragma unroll
        for (int ng = 0; ng < 8; ng++)
#pragma unroll
            for (int e = 0; e < 4; e++) acc[mt][ng][e] = 0.0f;

    if (tid == 0) {
#pragma unroll
        for (int s = 0; s < STAGES; s++)
            MBAR_INIT(sb + OFF_MBAR + s * 8, 1);
    }
    __syncthreads();

    // kick off B chunks 0..2 (chunk c+3 issued inside the loop)
    if (tid == 0) {
#pragma unroll
        for (int cc = 0; cc < 3; cc++) {
            MBAR_EXPECT_TX(sb + OFF_MBAR + cc * 8, B_CHUNK);
            bulk_copy(sb + OFF_B + (uint32_t)cc * B_CHUNK,
                      g_Bpre + (size_t)cc * B_CHUNK, B_CHUNK,
                      sb + OFF_MBAR + cc * 8);
        }
    }

    // ---- A: convert all 16 chunks to smem once ----
    // layout: [chunk 4096][part 2048][row*32 + ((unit ^ ((row>>2)&1))<<4)]
    {
        const int arow = tid >> 3;
        const int k32 = (tid & 7) * 32;
        const float* ap = emb + (size_t)(m0 + arow) * 512 + k32;
        const uint32_t rsw = (uint32_t)((arow >> 2) & 1);
#pragma unroll
        for (int uu = 0; uu < 4; uu++) {
            float4 v0 = *(const float4*)(ap + uu * 8);
            float4 v1 = *(const float4*)(ap + uu * 8 + 4);
            uint32_t h0, h1, h2, h3, l0, l1, l2, l3;
            split_f4(v0, h0, h1, l0, l1);
            split_f4(v1, h2, h3, l2, l3);
            const int kglob = k32 + uu * 8;
            const int ch = kglob >> 4;
            const uint32_t unitIdx = (uint32_t)((kglob >> 3) & 1);
            const uint32_t base = (uint32_t)ch * 4096 + (uint32_t)arow * 32
                                + ((unitIdx ^ rsw) << 4);
            *(uint4*)(smem + OFF_A + base)        = make_uint4(h0, h1, h2, h3);
            *(uint4*)(smem + OFF_A + base + 2048) = make_uint4(l0, l1, l2, l3);
        }
    }
    __syncthreads();   // A visible to all warps

    // lane addressing
    const uint32_t lrow = lane & 15, lchk = lane >> 4;
    // A: rows mw*32 + mt*16 + lrow ; swizzle bit depends only on lrow
    const uint32_t aLane = ((uint32_t)mw * 32 + lrow) * 32
                         + ((lchk ^ ((lrow >> 2) & 1)) << 4);
    const uint32_t bRow = lrow * 1024;
    const uint32_t swz  = lrow & 7;
    const uint32_t uW   = (uint32_t)nw * 8 + lchk;   // + un*2

#pragma unroll 1
    for (int c = 0; c < NCHUNK; ++c) {
        const int s = c & 3;
        MBAR_WAIT(sb + OFF_MBAR + s * 8, (c >> 2) & 1);   // B(c) landed
        __syncthreads();   // all warps past chunk c-1's LDSMs -> stage (c+3)&3 free

        if (tid == 0 && c + 3 < NCHUNK) {
            const int cN = c + 3, sN = cN & 3;
            MBAR_EXPECT_TX(sb + OFF_MBAR + sN * 8, B_CHUNK);
            bulk_copy(sb + OFF_B + (uint32_t)sN * B_CHUNK,
                      g_Bpre + (size_t)cN * B_CHUNK, B_CHUNK,
                      sb + OFF_MBAR + sN * 8);
        }

        const uint32_t aCh = sb + OFF_A + (uint32_t)c * 4096 + aLane;
        uint32_t Ah[2][4], Al[2][4];
#pragma unroll
        for (int mt = 0; mt < 2; mt++) {
            ldsm4(Ah[mt], aCh + (uint32_t)mt * 512);           // 16 rows x 32B
            ldsm4(Al[mt], aCh + (uint32_t)mt * 512 + 2048);
        }
        const uint32_t bH = sb + OFF_B + (uint32_t)s * B_CHUNK + bRow;
#pragma unroll
        for (int un = 0; un < 4; un++) {
            const uint32_t u = uW + (uint32_t)un * 2;
            const uint32_t addrH = bH + ((u ^ swz) << 4);
            uint32_t Bh[4], Bl[4];
            ldsm4t(Bh, addrH);
            ldsm4t(Bl, addrH + 16384);
#pragma unroll
            for (int mt = 0; mt < 2; mt++) {
#pragma unroll
                for (int nn = 0; nn < 2; nn++) {
                    float* d = acc[mt][un * 2 + nn];
                    mma16816(d, Ah[mt], Bh[nn * 2], Bh[nn * 2 + 1]);
                    mma16816(d, Ah[mt], Bl[nn * 2], Bl[nn * 2 + 1]);
                    mma16816(d, Al[mt], Bh[nn * 2], Bh[nn * 2 + 1]);
                }
            }
        }
    }

    // ======== fused epilogue: +bias, LayerNorm(512), *gamma+beta, ReLU ========
    const int g = lane >> 2, t4 = lane & 3;
    float* ps = (float*)(smem + OFF_PS);      // [64 rows][8 nw]
    float* pq = (float*)(smem + OFF_PQ);
    float2* mz = (float2*)(smem + OFF_MZ);    // [64] {mu, rstd}

    float sA[4] = {0.f, 0.f, 0.f, 0.f}, qA[4] = {0.f, 0.f, 0.f, 0.f};
#pragma unroll
    for (int mt = 0; mt < 2; mt++) {
#pragma unroll
        for (int ng = 0; ng < 8; ng++) {
            const int col = nw * 64 + ng * 8 + t4 * 2;
            const float2 bv = *(const float2*)(bias + col);
            acc[mt][ng][0] += bv.x; acc[mt][ng][1] += bv.y;
            acc[mt][ng][2] += bv.x; acc[mt][ng][3] += bv.y;
            sA[mt * 2 + 0] += acc[mt][ng][0] + acc[mt][ng][1];
            qA[mt * 2 + 0] += acc[mt][ng][0] * acc[mt][ng][0]
                            + acc[mt][ng][1] * acc[mt][ng][1];
            sA[mt * 2 + 1] += acc[mt][ng][2] + acc[mt][ng][3];
            qA[mt * 2 + 1] += acc[mt][ng][2] * acc[mt][ng][2]
                            + acc[mt][ng][3] * acc[mt][ng][3];
        }
    }
#pragma unroll
    for (int r4 = 0; r4 < 4; r4++) {
        sA[r4] += __shfl_xor_sync(0xffffffffu, sA[r4], 1);
        qA[r4] += __shfl_xor_sync(0xffffffffu, qA[r4], 1);
        sA[r4] += __shfl_xor_sync(0xffffffffu, sA[r4], 2);
        qA[r4] += __shfl_xor_sync(0xffffffffu, qA[r4], 2);
    }
    if (t4 == 0) {
#pragma unroll
        for (int r4 = 0; r4 < 4; r4++) {
            const int row = mw * 32 + (r4 >> 1) * 16 + (r4 & 1) * 8 + g;
            ps[row * 8 + nw] = sA[r4];
            pq[row * 8 + nw] = qA[r4];
        }
    }
    __syncthreads();
    if (tid < 64) {
        float ss = 0.f, qq = 0.f;
#pragma unroll
        for (int w = 0; w < 8; w++) { ss += ps[tid * 8 + w]; qq += pq[tid * 8 + w]; }
        const float mu  = ss * (1.0f / 512.0f);
        const float var = qq * (1.0f / 512.0f) - mu * mu;
        mz[tid] = make_float2(mu, rsqrtf(var + 1e-5f));
    }
    __syncthreads();

#pragma unroll
    for (int mt = 0; mt < 2; mt++) {
#pragma unroll
        for (int h = 0; h < 2; h++) {
            const int row = mw * 32 + mt * 16 + h * 8 + g;
            const float2 m = mz[row];
#pragma unroll
            for (int ng = 0; ng < 8; ng++) {
                const int col = nw * 64 + ng * 8 + t4 * 2;
                const float2 gv = *(const float2*)(gamma + col);
                const float2 tv = *(const float2*)(beta + col);
                const float v0 = acc[mt][ng][h * 2 + 0];
                const float v1 = acc[mt][ng][h * 2 + 1];
                const float o0 = fmaxf((v0 - m.x) * m.y * gv.x + tv.x, 0.0f);
                const float o1 = fmaxf((v1 - m.x) * m.y * gv.y + tv.y, 0.0f);
                *(float2*)(out + (size_t)(m0 + row) * 512 + col) = make_float2(o0, o1);
            }
        }
    }
}

extern "C" void kernel_launch(void* const* d_in, const int* in_sizes, int n_in,
                              void* d_out, int out_size)
{
    // metadata order: embeddings, W_proj, b_proj, W_enc, b_enc, ln_gamma, ln_beta
    const float* emb   = (const float*)d_in[0];
    const float* W_enc = (const float*)d_in[3];
    const float* b_enc = (const float*)d_in[4];
    const float* gam   = (const float*)d_in[5];
    const float* bet   = (const float*)d_in[6];
    float* out = (float*)d_out;

    prep_b_kernel<<<128, 256>>>(W_enc);

    cudaFuncSetAttribute(gemm_ln_kernel,
                         cudaFuncAttributeMaxDynamicSharedMemorySize, SMEM_TOTAL);
    gemm_ln_kernel<<<16384 / MTILE, THREADS, SMEM_TOTAL>>>(emb, b_enc, gam, bet, out);
}

// round 11
// speedup vs baseline: 1.1599x; 1.1599x over previous
#include <cuda_runtime.h>
#include <cuda_bf16.h>
#include <cstdint>

// ============================================================================
// SimplifiedTopologyExtractor — algebraic reduction:
//   out = ReLU(LayerNorm(emb[:, :, :256] @ W_enc + b_enc))
// (pooled == embeddings exactly; proj/cdist/topk is dead code.)
//
// fp32 GEMM via bf16 hi/lo split on mma.sync m16n8k16:
//   a*b ≈ ah*bh + ah*bl + al*bh   (err ~2^-18 rel).
// Round 11 = R8 champion + two anti-phase-serialization changes:
//   (1) KCH 16->32: 8 chunk boundaries instead of 16 (halved sync overhead)
//   (2) register double-buffered B fragments: ldsm for step j+1 issued
//       before MMAs of step j, overlapping crossbar with tensor per-warp.
// ============================================================================

#define THREADS 512
#define MTILE 64
#define KD 256
#define KCH 32
#define NCHUNK (KD / KCH)      // 8
#define B_CHUNK 65536          // [part 2][kr 32][1024B], XOR-unit swizzled

// A stage: [ks 2][part 2][64 rows x 48B]  (16-k sub-blocks, R8-proven layout)
#define A_STAGE 12288
// smem layout (bytes)
#define OFF_A     0                          // 2 stages x 12288
#define OFF_B     24576                      // 2 stages x 65536
#define OFF_MBAR  (OFF_B + 2 * B_CHUNK)      // 155648
#define OFF_PS    (OFF_MBAR + 64)
#define OFF_PQ    (OFF_PS + 1024)
#define OFF_MZ    (OFF_PQ + 1024)
#define SMEM_TOTAL (OFF_MZ + 512)            // 158272

// prepped B (bf16 hi/lo): [chunk 8][part 2][kr 32][unit 64], unit^=(kr&7)
__device__ __align__(128) unsigned char g_Bpre[8 * B_CHUNK];   // 512 KB

__device__ __forceinline__ uint32_t smem_u32(const void* p) {
    uint32_t a;
    asm("{ .reg .u64 t; cvta.to.shared.u64 t, %1; cvt.u32.u64 %0, t; }"
        : "=r"(a) : "l"(p));
    return a;
}

__device__ __forceinline__ void ldsm4(uint32_t* r, uint32_t addr) {
    asm volatile("ldmatrix.sync.aligned.m8n8.x4.shared.b16 {%0,%1,%2,%3}, [%4];"
                 : "=r"(r[0]), "=r"(r[1]), "=r"(r[2]), "=r"(r[3]) : "r"(addr));
}
__device__ __forceinline__ void ldsm4t(uint32_t* r, uint32_t addr) {
    asm volatile("ldmatrix.sync.aligned.m8n8.x4.trans.shared.b16 {%0,%1,%2,%3}, [%4];"
                 : "=r"(r[0]), "=r"(r[1]), "=r"(r[2]), "=r"(r[3]) : "r"(addr));
}

__device__ __forceinline__ void mma16816(float* d, const uint32_t* a,
                                         uint32_t b0, uint32_t b1) {
    asm volatile(
        "mma.sync.aligned.m16n8k16.row.col.f32.bf16.bf16.f32 "
        "{%0,%1,%2,%3}, {%4,%5,%6,%7}, {%8,%9}, {%0,%1,%2,%3};"
        : "+f"(d[0]), "+f"(d[1]), "+f"(d[2]), "+f"(d[3])
        : "r"(a[0]), "r"(a[1]), "r"(a[2]), "r"(a[3]), "r"(b0), "r"(b1));
}

#define MBAR_INIT(addr, cnt) \
    asm volatile("mbarrier.init.shared.b64 [%0], %1;" :: "r"(addr), "r"(cnt) : "memory")

#define MBAR_EXPECT_TX(addr, bytes) \
    asm volatile("mbarrier.arrive.expect_tx.shared.b64 _, [%0], %1;" \
                 :: "r"(addr), "r"((uint32_t)(bytes)) : "memory")

#define MBAR_WAIT(addr, par) do {                                              \
    uint32_t _m = (addr), _p = (uint32_t)(par), _done;                         \
    asm volatile("{\n\t.reg .pred p;\n\t"                                      \
        "mbarrier.try_wait.parity.acquire.cta.shared::cta.b64 p, [%1], %2;\n\t"\
        "selp.b32 %0, 1, 0, p;\n\t}" : "=r"(_done) : "r"(_m), "r"(_p) : "memory"); \
    if (!_done) {                                                              \
        asm volatile("{\n\t.reg .pred P1;\n\t"                                 \
            "W%=:\n\t"                                                         \
            "mbarrier.try_wait.parity.acquire.cta.shared::cta.b64 P1, [%0], %1, 0x989680;\n\t" \
            "@P1 bra.uni D%=;\n\t"                                             \
            "bra.uni W%=;\n\t"                                                 \
            "D%=:\n\t}" :: "r"(_m), "r"(_p) : "memory");                       \
    }                                                                          \
} while (0)

__device__ __forceinline__ void bulk_copy(uint32_t dst, const void* src,
                                          uint32_t bytes, uint32_t mbar) {
    asm volatile(
        "cp.async.bulk.shared::cluster.global.mbarrier::complete_tx::bytes "
        "[%0], [%1], %2, [%3];"
        :: "r"(dst), "l"(src), "r"(bytes), "r"(mbar) : "memory");
}

__device__ __forceinline__ void split_f4(float4 v, uint32_t& h01, uint32_t& h23,
                                         uint32_t& l01, uint32_t& l23) {
    float f[4] = {v.x, v.y, v.z, v.w};
    unsigned short hs[4], ls[4];
#pragma unroll
    for (int i = 0; i < 4; i++) {
        __nv_bfloat16 h = __float2bfloat16(f[i]);
        float rem = f[i] - __bfloat162float(h);
        __nv_bfloat16 l = __float2bfloat16(rem);
        hs[i] = __bfloat16_as_ushort(h);
        ls[i] = __bfloat16_as_ushort(l);
    }
    h01 = (uint32_t)hs[0] | ((uint32_t)hs[1] << 16);
    h23 = (uint32_t)hs[2] | ((uint32_t)hs[3] << 16);
    l01 = (uint32_t)ls[0] | ((uint32_t)ls[1] << 16);
    l23 = (uint32_t)ls[2] | ((uint32_t)ls[3] << 16);
}

// ---- prep B: W_enc[256,512] -> hi/lo bf16, chunk-tiled + XOR swizzle ----
__global__ void prep_b_kernel(const float* __restrict__ W) {
    int t = blockIdx.x * 256 + threadIdx.x;   // 256 k x 128 nq
    int k  = t >> 7;
    int nq = t & 127;
    float4 v = *(const float4*)(W + (size_t)k * 512 + nq * 4);
    uint32_t h01, h23, l01, l23;
    split_f4(v, h01, h23, l01, l23);
    int c = k >> 5, kr = k & 31;
    int unit = nq >> 1;
    int sw   = unit ^ (kr & 7);
    size_t base = (size_t)c * B_CHUNK + (size_t)kr * 1024
                + (size_t)sw * 16 + (nq & 1) * 8;
    *(uint2*)(g_Bpre + base)         = make_uint2(h01, h23);
    *(uint2*)(g_Bpre + base + 32768) = make_uint2(l01, l23);
}

// ---- GEMM + fused bias/LayerNorm/ReLU ----
__global__ void __launch_bounds__(THREADS, 1)
gemm_ln_kernel(const float* __restrict__ emb,
               const float* __restrict__ bias,
               const float* __restrict__ gamma,
               const float* __restrict__ beta,
               float* __restrict__ out)
{
    extern __shared__ __align__(1024) unsigned char smem[];
    const uint32_t sb = smem_u32(smem);
    const int tid = threadIdx.x;
    const int wid = tid >> 5;
    const int lane = tid & 31;
    const int mw = wid >> 2;       // 4 m-warps: rows mw*16..+16
    const int nw = wid & 3;        // 4 n-warps: cols nw*128..+128
    const int m0 = blockIdx.x * MTILE;

    float acc[16][4];
#pragma unroll
    for (int nt = 0; nt < 16; nt++)
#pragma unroll
        for (int e = 0; e < 4; e++) acc[nt][e] = 0.0f;

    if (tid == 0) {
        MBAR_INIT(sb + OFF_MBAR + 0, 1);
        MBAR_INIT(sb + OFF_MBAR + 8, 1);
    }
    __syncthreads();

    // A staging: thread owns one float4 (4 k) of the 64x32 chunk
    const int a_row = tid >> 3;
    const int a_kq  = tid & 7;            // 8 float4 per row = 32 k
    const int a_ks  = a_kq >> 2;          // 16-k sub-block
    const int a_kk  = a_kq & 3;
    const float* a_src = emb + (size_t)(m0 + a_row) * 512 + a_kq * 4;
    const uint32_t a_off = (uint32_t)a_ks * 6144
                         + (uint32_t)a_row * 48 + (uint32_t)a_kk * 8;

#define STS_A(stg, v) do {                                                      \
    uint32_t _h01, _h23, _l01, _l23;                                            \
    split_f4((v), _h01, _h23, _l01, _l23);                                      \
    const uint32_t _b = (uint32_t)(stg) * A_STAGE + a_off;                      \
    *(uint2*)(smem + OFF_A + _b)        = make_uint2(_h01, _h23);               \
    *(uint2*)(smem + OFF_A + _b + 3072) = make_uint2(_l01, _l23);               \
} while (0)

    // ---- prologue: stage 0 ----
    {
        float4 a0 = *(const float4*)(a_src);
        STS_A(0, a0);
    }
    if (tid == 0) {
        MBAR_EXPECT_TX(sb + OFF_MBAR + 0, B_CHUNK);
        bulk_copy(sb + OFF_B, g_Bpre, B_CHUNK, sb + OFF_MBAR + 0);
    }
    float4 aR = *(const float4*)(a_src + 32);

    // lane addressing
    const uint32_t lrow = lane & 15, lchk = lane >> 4;
    const uint32_t aLane = ((uint32_t)mw * 16 + lrow) * 48 + lchk * 16;
    const uint32_t bRow = lrow * 1024;
    const uint32_t swz  = lrow & 7;
    const uint32_t uBase = (uint32_t)nw * 16 + lchk;

#pragma unroll 1
    for (int c = 0; c < NCHUNK; ++c) {
        const int s = c & 1;
        MBAR_WAIT(sb + OFF_MBAR + s * 8, (c >> 1) & 1);   // B(c) landed
        __syncthreads();   // A(c) visible; stage s^1 fully consumed

        if (c + 1 < NCHUNK) {
            STS_A(s ^ 1, aR);
            if (tid == 0) {
                MBAR_EXPECT_TX(sb + OFF_MBAR + (s ^ 1) * 8, B_CHUNK);
                bulk_copy(sb + OFF_B + (uint32_t)(s ^ 1) * B_CHUNK,
                          g_Bpre + (size_t)(c + 1) * B_CHUNK, B_CHUNK,
                          sb + OFF_MBAR + (s ^ 1) * 8);
            }
        }
        if (c + 2 < NCHUNK) aR = *(const float4*)(a_src + (c + 2) * 32);

        const uint32_t stA = sb + OFF_A + (uint32_t)s * A_STAGE;
        const uint32_t stB = sb + OFF_B + (uint32_t)s * B_CHUNK;

        // A fragments for both 16-k sub-blocks
        uint32_t Ah[2][4], Al[2][4];
#pragma unroll
        for (int ks = 0; ks < 2; ks++) {
            ldsm4(Ah[ks], stA + (uint32_t)ks * 6144 + aLane);
            ldsm4(Al[ks], stA + (uint32_t)ks * 6144 + aLane + 3072);
        }

#pragma unroll
        for (int ks = 0; ks < 2; ks++) {
            const uint32_t bH = stB + (uint32_t)ks * 16384 + bRow;
            // register double-buffered B fragments: load j+1 before MMA(j)
            uint32_t Bh[2][4], Bl[2][4];
            {
                const uint32_t a0 = bH + ((uBase ^ swz) << 4);
                ldsm4t(Bh[0], a0);
                ldsm4t(Bl[0], a0 + 32768);
            }
#pragma unroll
            for (int j = 0; j < 8; j++) {
                const int cu = j & 1, nx = cu ^ 1;
                if (j < 7) {
                    const uint32_t u = uBase + (uint32_t)(j + 1) * 2;
                    const uint32_t ad = bH + ((u ^ swz) << 4);
                    ldsm4t(Bh[nx], ad);
                    ldsm4t(Bl[nx], ad + 32768);
                }
#pragma unroll
                for (int nn = 0; nn < 2; nn++) {
                    float* d = acc[j * 2 + nn];
                    mma16816(d, Ah[ks], Bh[cu][nn * 2], Bh[cu][nn * 2 + 1]);
                    mma16816(d, Ah[ks], Bl[cu][nn * 2], Bl[cu][nn * 2 + 1]);
                    mma16816(d, Al[ks], Bh[cu][nn * 2], Bh[cu][nn * 2 + 1]);
                }
            }
        }
    }

    // ======== fused epilogue: +bias, LayerNorm(512), *gamma+beta, ReLU ========
    const int g = lane >> 2, t4 = lane & 3;
    float* ps = (float*)(smem + OFF_PS);      // [64 rows][4 nw]
    float* pq = (float*)(smem + OFF_PQ);
    float2* mz = (float2*)(smem + OFF_MZ);    // [64] {mu, rstd}

    float sA[2] = {0.f, 0.f}, qA[2] = {0.f, 0.f};
#pragma unroll
    for (int nt = 0; nt < 16; nt++) {
        const int col = nw * 128 + nt * 8 + t4 * 2;
        const float2 bv = *(const float2*)(bias + col);
        acc[nt][0] += bv.x; acc[nt][1] += bv.y;
        acc[nt][2] += bv.x; acc[nt][3] += bv.y;
        sA[0] += acc[nt][0] + acc[nt][1];
        qA[0] += acc[nt][0] * acc[nt][0] + acc[nt][1] * acc[nt][1];
        sA[1] += acc[nt][2] + acc[nt][3];
        qA[1] += acc[nt][2] * acc[nt][2] + acc[nt][3] * acc[nt][3];
    }
#pragma unroll
    for (int h = 0; h < 2; h++) {
        sA[h] += __shfl_xor_sync(0xffffffffu, sA[h], 1);
        qA[h] += __shfl_xor_sync(0xffffffffu, qA[h], 1);
        sA[h] += __shfl_xor_sync(0xffffffffu, sA[h], 2);
        qA[h] += __shfl_xor_sync(0xffffffffu, qA[h], 2);
    }
    if (t4 == 0) {
#pragma unroll
        for (int h = 0; h < 2; h++) {
            const int row = mw * 16 + h * 8 + g;
            ps[row * 4 + nw] = sA[h];
            pq[row * 4 + nw] = qA[h];
        }
    }
    __syncthreads();
    if (tid < 64) {
        float ss = ps[tid * 4 + 0] + ps[tid * 4 + 1]
                 + ps[tid * 4 + 2] + ps[tid * 4 + 3];
        float qq = pq[tid * 4 + 0] + pq[tid * 4 + 1]
                 + pq[tid * 4 + 2] + pq[tid * 4 + 3];
        const float mu  = ss * (1.0f / 512.0f);
        const float var = qq * (1.0f / 512.0f) - mu * mu;
        mz[tid] = make_float2(mu, rsqrtf(var + 1e-5f));
    }
    __syncthreads();

#pragma unroll
    for (int h = 0; h < 2; h++) {
        const int row = mw * 16 + h * 8 + g;
        const float2 m = mz[row];
#pragma unroll
        for (int nt = 0; nt < 16; nt++) {
            const int col = nw * 128 + nt * 8 + t4 * 2;
            const float2 gv = *(const float2*)(gamma + col);
            const float2 tv = *(const float2*)(beta + col);
            const float v0 = acc[nt][h * 2 + 0];
            const float v1 = acc[nt][h * 2 + 1];
            const float o0 = fmaxf((v0 - m.x) * m.y * gv.x + tv.x, 0.0f);
            const float o1 = fmaxf((v1 - m.x) * m.y * gv.y + tv.y, 0.0f);
            *(float2*)(out + (size_t)(m0 + row) * 512 + col) = make_float2(o0, o1);
        }
    }
}

extern "C" void kernel_launch(void* const* d_in, const int* in_sizes, int n_in,
                              void* d_out, int out_size)
{
    // metadata order: embeddings, W_proj, b_proj, W_enc, b_enc, ln_gamma, ln_beta
    const float* emb   = (const float*)d_in[0];
    const float* W_enc = (const float*)d_in[3];
    const float* b_enc = (const float*)d_in[4];
    const float* gam   = (const float*)d_in[5];
    const float* bet   = (const float*)d_in[6];
    float* out = (float*)d_out;

    prep_b_kernel<<<128, 256>>>(W_enc);

    cudaFuncSetAttribute(gemm_ln_kernel,
                         cudaFuncAttributeMaxDynamicSharedMemorySize, SMEM_TOTAL);
    gemm_ln_kernel<<<16384 / MTILE, THREADS, SMEM_TOTAL>>>(emb, b_enc, gam, bet, out);
}

// round 12
// speedup vs baseline: 1.2563x; 1.0831x over previous
#include <cuda_runtime.h>
#include <cuda_bf16.h>
#include <cstdint>

// ============================================================================
// SimplifiedTopologyExtractor — algebraic reduction:
//   out = ReLU(LayerNorm(emb[:, :, :256] @ W_enc + b_enc))
// (pooled == embeddings exactly; proj/cdist/topk is dead code.)
//
// fp32 GEMM via bf16 hi/lo split on mma.sync m16n8k16:
//   a*b ≈ ah*bh + ah*bl + al*bh   (err ~2^-18 rel).
// Round 12 = R11 champion with ONLY the warp grid changed 4x4 -> 2x8
// (warp tile m32n64): B crossbar duplication 4x->2x (352->260KB/chunk)
// and 12 MMAs of latency cover per B fragment pair (was 6).
// ============================================================================

#define THREADS 512
#define MTILE 64
#define KD 256
#define KCH 32
#define NCHUNK (KD / KCH)      // 8
#define B_CHUNK 65536          // [part 2][kr 32][1024B], XOR-unit swizzled

// A stage: [ks 2][part 2][64 rows x 48B]
#define A_STAGE 12288
// smem layout (bytes)
#define OFF_A     0                          // 2 stages x 12288
#define OFF_B     24576                      // 2 stages x 65536
#define OFF_MBAR  (OFF_B + 2 * B_CHUNK)      // 155648
#define OFF_PS    (OFF_MBAR + 64)            // [64 rows][8 nw]
#define OFF_PQ    (OFF_PS + 2048)
#define OFF_MZ    (OFF_PQ + 2048)
#define SMEM_TOTAL (OFF_MZ + 512)            // 160320

// prepped B (bf16 hi/lo): [chunk 8][part 2][kr 32][unit 64], unit^=(kr&7)
__device__ __align__(128) unsigned char g_Bpre[8 * B_CHUNK];   // 512 KB

__device__ __forceinline__ uint32_t smem_u32(const void* p) {
    uint32_t a;
    asm("{ .reg .u64 t; cvta.to.shared.u64 t, %1; cvt.u32.u64 %0, t; }"
        : "=r"(a) : "l"(p));
    return a;
}

__device__ __forceinline__ void ldsm4(uint32_t* r, uint32_t addr) {
    asm volatile("ldmatrix.sync.aligned.m8n8.x4.shared.b16 {%0,%1,%2,%3}, [%4];"
                 : "=r"(r[0]), "=r"(r[1]), "=r"(r[2]), "=r"(r[3]) : "r"(addr));
}
__device__ __forceinline__ void ldsm4t(uint32_t* r, uint32_t addr) {
    asm volatile("ldmatrix.sync.aligned.m8n8.x4.trans.shared.b16 {%0,%1,%2,%3}, [%4];"
                 : "=r"(r[0]), "=r"(r[1]), "=r"(r[2]), "=r"(r[3]) : "r"(addr));
}

__device__ __forceinline__ void mma16816(float* d, const uint32_t* a,
                                         uint32_t b0, uint32_t b1) {
    asm volatile(
        "mma.sync.aligned.m16n8k16.row.col.f32.bf16.bf16.f32 "
        "{%0,%1,%2,%3}, {%4,%5,%6,%7}, {%8,%9}, {%0,%1,%2,%3};"
        : "+f"(d[0]), "+f"(d[1]), "+f"(d[2]), "+f"(d[3])
        : "r"(a[0]), "r"(a[1]), "r"(a[2]), "r"(a[3]), "r"(b0), "r"(b1));
}

#define MBAR_INIT(addr, cnt) \
    asm volatile("mbarrier.init.shared.b64 [%0], %1;" :: "r"(addr), "r"(cnt) : "memory")

#define MBAR_EXPECT_TX(addr, bytes) \
    asm volatile("mbarrier.arrive.expect_tx.shared.b64 _, [%0], %1;" \
                 :: "r"(addr), "r"((uint32_t)(bytes)) : "memory")

#define MBAR_WAIT(addr, par) do {                                              \
    uint32_t _m = (addr), _p = (uint32_t)(par), _done;                         \
    asm volatile("{\n\t.reg .pred p;\n\t"                                      \
        "mbarrier.try_wait.parity.acquire.cta.shared::cta.b64 p, [%1], %2;\n\t"\
        "selp.b32 %0, 1, 0, p;\n\t}" : "=r"(_done) : "r"(_m), "r"(_p) : "memory"); \
    if (!_done) {                                                              \
        asm volatile("{\n\t.reg .pred P1;\n\t"                                 \
            "W%=:\n\t"                                                         \
            "mbarrier.try_wait.parity.acquire.cta.shared::cta.b64 P1, [%0], %1, 0x989680;\n\t" \
            "@P1 bra.uni D%=;\n\t"                                             \
            "bra.uni W%=;\n\t"                                                 \
            "D%=:\n\t}" :: "r"(_m), "r"(_p) : "memory");                       \
    }                                                                          \
} while (0)

__device__ __forceinline__ void bulk_copy(uint32_t dst, const void* src,
                                          uint32_t bytes, uint32_t mbar) {
    asm volatile(
        "cp.async.bulk.shared::cluster.global.mbarrier::complete_tx::bytes "
        "[%0], [%1], %2, [%3];"
        :: "r"(dst), "l"(src), "r"(bytes), "r"(mbar) : "memory");
}

__device__ __forceinline__ void split_f4(float4 v, uint32_t& h01, uint32_t& h23,
                                         uint32_t& l01, uint32_t& l23) {
    float f[4] = {v.x, v.y, v.z, v.w};
    unsigned short hs[4], ls[4];
#pragma unroll
    for (int i = 0; i < 4; i++) {
        __nv_bfloat16 h = __float2bfloat16(f[i]);
        float rem = f[i] - __bfloat162float(h);
        __nv_bfloat16 l = __float2bfloat16(rem);
        hs[i] = __bfloat16_as_ushort(h);
        ls[i] = __bfloat16_as_ushort(l);
    }
    h01 = (uint32_t)hs[0] | ((uint32_t)hs[1] << 16);
    h23 = (uint32_t)hs[2] | ((uint32_t)hs[3] << 16);
    l01 = (uint32_t)ls[0] | ((uint32_t)ls[1] << 16);
    l23 = (uint32_t)ls[2] | ((uint32_t)ls[3] << 16);
}

// ---- prep B: W_enc[256,512] -> hi/lo bf16, chunk-tiled + XOR swizzle ----
__global__ void prep_b_kernel(const float* __restrict__ W) {
    int t = blockIdx.x * 256 + threadIdx.x;   // 256 k x 128 nq
    int k  = t >> 7;
    int nq = t & 127;
    float4 v = *(const float4*)(W + (size_t)k * 512 + nq * 4);
    uint32_t h01, h23, l01, l23;
    split_f4(v, h01, h23, l01, l23);
    int c = k >> 5, kr = k & 31;
    int unit = nq >> 1;
    int sw   = unit ^ (kr & 7);
    size_t base = (size_t)c * B_CHUNK + (size_t)kr * 1024
                + (size_t)sw * 16 + (nq & 1) * 8;
    *(uint2*)(g_Bpre + base)         = make_uint2(h01, h23);
    *(uint2*)(g_Bpre + base + 32768) = make_uint2(l01, l23);
}

// ---- GEMM + fused bias/LayerNorm/ReLU ----
__global__ void __launch_bounds__(THREADS, 1)
gemm_ln_kernel(const float* __restrict__ emb,
               const float* __restrict__ bias,
               const float* __restrict__ gamma,
               const float* __restrict__ beta,
               float* __restrict__ out)
{
    extern __shared__ __align__(1024) unsigned char smem[];
    const uint32_t sb = smem_u32(smem);
    const int tid = threadIdx.x;
    const int wid = tid >> 5;
    const int lane = tid & 31;
    const int mw = wid >> 3;       // 2 m-warps: rows mw*32..+32
    const int nw = wid & 7;        // 8 n-warps: cols nw*64..+64
    const int m0 = blockIdx.x * MTILE;

    float acc[2][8][4];            // [mt][j*2+nn][frag]
#pragma unroll
    for (int mt = 0; mt < 2; mt++)
#pragma unroll
        for (int ng = 0; ng < 8; ng++)
#pragma unroll
            for (int e = 0; e < 4; e++) acc[mt][ng][e] = 0.0f;

    if (tid == 0) {
        MBAR_INIT(sb + OFF_MBAR + 0, 1);
        MBAR_INIT(sb + OFF_MBAR + 8, 1);
    }
    __syncthreads();

    // A staging: thread owns one float4 (4 k) of the 64x32 chunk
    const int a_row = tid >> 3;
    const int a_kq  = tid & 7;
    const int a_ks  = a_kq >> 2;
    const int a_kk  = a_kq & 3;
    const float* a_src = emb + (size_t)(m0 + a_row) * 512 + a_kq * 4;
    const uint32_t a_off = (uint32_t)a_ks * 6144
                         + (uint32_t)a_row * 48 + (uint32_t)a_kk * 8;

#define STS_A(stg, v) do {                                                      \
    uint32_t _h01, _h23, _l01, _l23;                                            \
    split_f4((v), _h01, _h23, _l01, _l23);                                      \
    const uint32_t _b = (uint32_t)(stg) * A_STAGE + a_off;                      \
    *(uint2*)(smem + OFF_A + _b)        = make_uint2(_h01, _h23);               \
    *(uint2*)(smem + OFF_A + _b + 3072) = make_uint2(_l01, _l23);               \
} while (0)

    // ---- prologue: stage 0 ----
    {
        float4 a0 = *(const float4*)(a_src);
        STS_A(0, a0);
    }
    if (tid == 0) {
        MBAR_EXPECT_TX(sb + OFF_MBAR + 0, B_CHUNK);
        bulk_copy(sb + OFF_B, g_Bpre, B_CHUNK, sb + OFF_MBAR + 0);
    }
    float4 aR = *(const float4*)(a_src + 32);

    // lane addressing
    const uint32_t lrow = lane & 15, lchk = lane >> 4;
    // A rows: mw*32 + mt*16 + lrow, 48B stride; mt adds 768B
    const uint32_t aLane = ((uint32_t)mw * 32 + lrow) * 48 + lchk * 16;
    const uint32_t bRow = lrow * 1024;
    const uint32_t swz  = lrow & 7;
    const uint32_t uBase = (uint32_t)nw * 8 + lchk;   // 8 units = 64 cols/warp

#pragma unroll 1
    for (int c = 0; c < NCHUNK; ++c) {
        const int s = c & 1;
        MBAR_WAIT(sb + OFF_MBAR + s * 8, (c >> 1) & 1);   // B(c) landed
        __syncthreads();   // A(c) visible; stage s^1 fully consumed

        if (c + 1 < NCHUNK) {
            STS_A(s ^ 1, aR);
            if (tid == 0) {
                MBAR_EXPECT_TX(sb + OFF_MBAR + (s ^ 1) * 8, B_CHUNK);
                bulk_copy(sb + OFF_B + (uint32_t)(s ^ 1) * B_CHUNK,
                          g_Bpre + (size_t)(c + 1) * B_CHUNK, B_CHUNK,
                          sb + OFF_MBAR + (s ^ 1) * 8);
            }
        }
        if (c + 2 < NCHUNK) aR = *(const float4*)(a_src + (c + 2) * 32);

        const uint32_t stA = sb + OFF_A + (uint32_t)s * A_STAGE;
        const uint32_t stB = sb + OFF_B + (uint32_t)s * B_CHUNK;

#pragma unroll
        for (int ks = 0; ks < 2; ks++) {
            // A fragments for this 16-k sub-block: m32 = 2 x m16
            uint32_t Ah[2][4], Al[2][4];
#pragma unroll
            for (int mt = 0; mt < 2; mt++) {
                const uint32_t aAd = stA + (uint32_t)ks * 6144 + aLane
                                   + (uint32_t)mt * 768;
                ldsm4(Ah[mt], aAd);
                ldsm4(Al[mt], aAd + 3072);
            }

            const uint32_t bH = stB + (uint32_t)ks * 16384 + bRow;
            // register double-buffered B fragments: load j+1 before MMA(j)
            uint32_t Bh[2][4], Bl[2][4];
            {
                const uint32_t a0 = bH + ((uBase ^ swz) << 4);
                ldsm4t(Bh[0], a0);
                ldsm4t(Bl[0], a0 + 32768);
            }
#pragma unroll
            for (int j = 0; j < 4; j++) {
                const int cu = j & 1, nx = cu ^ 1;
                if (j < 3) {
                    const uint32_t u = uBase + (uint32_t)(j + 1) * 2;
                    const uint32_t ad = bH + ((u ^ swz) << 4);
                    ldsm4t(Bh[nx], ad);
                    ldsm4t(Bl[nx], ad + 32768);
                }
#pragma unroll
                for (int mt = 0; mt < 2; mt++) {
#pragma unroll
                    for (int nn = 0; nn < 2; nn++) {
                        float* d = acc[mt][j * 2 + nn];
                        mma16816(d, Ah[mt], Bh[cu][nn * 2], Bh[cu][nn * 2 + 1]);
                        mma16816(d, Ah[mt], Bl[cu][nn * 2], Bl[cu][nn * 2 + 1]);
                        mma16816(d, Al[mt], Bh[cu][nn * 2], Bh[cu][nn * 2 + 1]);
                    }
                }
            }
        }
    }

    // ======== fused epilogue: +bias, LayerNorm(512), *gamma+beta, ReLU ========
    const int g = lane >> 2, t4 = lane & 3;
    float* ps = (float*)(smem + OFF_PS);      // [64 rows][8 nw]
    float* pq = (float*)(smem + OFF_PQ);
    float2* mz = (float2*)(smem + OFF_MZ);    // [64] {mu, rstd}

    float sA[4] = {0.f, 0.f, 0.f, 0.f}, qA[4] = {0.f, 0.f, 0.f, 0.f};
#pragma unroll
    for (int mt = 0; mt < 2; mt++) {
#pragma unroll
        for (int ng = 0; ng < 8; ng++) {
            const int col = nw * 64 + ng * 8 + t4 * 2;
            const float2 bv = *(const float2*)(bias + col);
            acc[mt][ng][0] += bv.x; acc[mt][ng][1] += bv.y;
            acc[mt][ng][2] += bv.x; acc[mt][ng][3] += bv.y;
            sA[mt * 2 + 0] += acc[mt][ng][0] + acc[mt][ng][1];
            qA[mt * 2 + 0] += acc[mt][ng][0] * acc[mt][ng][0]
                            + acc[mt][ng][1] * acc[mt][ng][1];
            sA[mt * 2 + 1] += acc[mt][ng][2] + acc[mt][ng][3];
            qA[mt * 2 + 1] += acc[mt][ng][2] * acc[mt][ng][2]
                            + acc[mt][ng][3] * acc[mt][ng][3];
        }
    }
#pragma unroll
    for (int r4 = 0; r4 < 4; r4++) {
        sA[r4] += __shfl_xor_sync(0xffffffffu, sA[r4], 1);
        qA[r4] += __shfl_xor_sync(0xffffffffu, qA[r4], 1);
        sA[r4] += __shfl_xor_sync(0xffffffffu, sA[r4], 2);
        qA[r4] += __shfl_xor_sync(0xffffffffu, qA[r4], 2);
    }
    if (t4 == 0) {
#pragma unroll
        for (int r4 = 0; r4 < 4; r4++) {
            const int row = mw * 32 + (r4 >> 1) * 16 + (r4 & 1) * 8 + g;
            ps[row * 8 + nw] = sA[r4];
            pq[row * 8 + nw] = qA[r4];
        }
    }
    __syncthreads();
    if (tid < 64) {
        float ss = 0.f, qq = 0.f;
#pragma unroll
        for (int w = 0; w < 8; w++) { ss += ps[tid * 8 + w]; qq += pq[tid * 8 + w]; }
        const float mu  = ss * (1.0f / 512.0f);
        const float var = qq * (1.0f / 512.0f) - mu * mu;
        mz[tid] = make_float2(mu, rsqrtf(var + 1e-5f));
    }
    __syncthreads();

#pragma unroll
    for (int mt = 0; mt < 2; mt++) {
#pragma unroll
        for (int h = 0; h < 2; h++) {
            const int row = mw * 32 + mt * 16 + h * 8 + g;
            const float2 m = mz[row];
#pragma unroll
            for (int ng = 0; ng < 8; ng++) {
                const int col = nw * 64 + ng * 8 + t4 * 2;
                const float2 gv = *(const float2*)(gamma + col);
                const float2 tv = *(const float2*)(beta + col);
                const float v0 = acc[mt][ng][h * 2 + 0];
                const float v1 = acc[mt][ng][h * 2 + 1];
                const float o0 = fmaxf((v0 - m.x) * m.y * gv.x + tv.x, 0.0f);
                const float o1 = fmaxf((v1 - m.x) * m.y * gv.y + tv.y, 0.0f);
                *(float2*)(out + (size_t)(m0 + row) * 512 + col) = make_float2(o0, o1);
            }
        }
    }
}

extern "C" void kernel_launch(void* const* d_in, const int* in_sizes, int n_in,
                              void* d_out, int out_size)
{
    // metadata order: embeddings, W_proj, b_proj, W_enc, b_enc, ln_gamma, ln_beta
    const float* emb   = (const float*)d_in[0];
    const float* W_enc = (const float*)d_in[3];
    const float* b_enc = (const float*)d_in[4];
    const float* gam   = (const float*)d_in[5];
    const float* bet   = (const float*)d_in[6];
    float* out = (float*)d_out;

    prep_b_kernel<<<128, 256>>>(W_enc);

    cudaFuncSetAttribute(gemm_ln_kernel,
                         cudaFuncAttributeMaxDynamicSharedMemorySize, SMEM_TOTAL);
    gemm_ln_kernel<<<16384 / MTILE, THREADS, SMEM_TOTAL>>>(emb, b_enc, gam, bet, out);
}